// round 1
// baseline (speedup 1.0000x reference)
#include <cuda_runtime.h>
#include <cstdint>

// Problem constants (fixed by dataset):
//   x      [B=4, C=64, T=1000, F=96]  f32
//   weight [F=96, C*5=320, O=2]       f32   (flattened (C,tc) C-major: idx = c*5+k)
//   bias   [F=96, O=2]                f32
//   out    [B=4, O=2, T=1000, F=96]   f32
// out[b,o,t,f] = sum_{c,k} x[b,c,t-4+k,f] * w[f, c*5+k, o] + bias[f,o]   (x zero-padded for t<0)

#define FD 96
#define CD 64
#define TD 1000
#define TC 5
#define TT 20                 // output t per tile
#define ROWS (TT + TC - 1)    // 24 slab rows (includes 4-row causal halo)
#define TPG 10                // t per thread
#define NTHREADS 192          // 96 f-lanes x 2 t-groups
#define NTILES (TD / TT)      // 50

__device__ __forceinline__ unsigned long long pack2(float lo, float hi) {
    unsigned long long r;
    asm("mov.b64 %0, {%1, %2};" : "=l"(r) : "f"(lo), "f"(hi));
    return r;
}
__device__ __forceinline__ void unpack2(unsigned long long v, float& lo, float& hi) {
    asm("mov.b64 {%0, %1}, %2;" : "=f"(lo), "=f"(hi) : "l"(v));
}
// Blackwell packed f32x2 FMA: two fp32 lanes per instruction (halves FFMA issue count)
__device__ __forceinline__ void ffma2(unsigned long long& d, unsigned long long a, unsigned long long b) {
    asm("fma.rn.f32x2 %0, %1, %2, %0;" : "+l"(d) : "l"(a), "l"(b));
}
__device__ __forceinline__ void cp_async16(void* sm, const void* gm) {
    unsigned s = (unsigned)__cvta_generic_to_shared(sm);
    asm volatile("cp.async.cg.shared.global [%0], [%1], 16;\n" :: "r"(s), "l"(gm));
}

__global__ __launch_bounds__(NTHREADS)
void decoder_out_kernel(const float* __restrict__ x,
                        const float* __restrict__ w,
                        const float* __restrict__ bias,
                        float* __restrict__ out)
{
    __shared__ __align__(16) float slab[2][ROWS][FD];

    const int tid  = threadIdx.x;
    const int f    = tid % FD;          // frequency lane
    const int tg   = tid / FD;          // t-group (0/1)
    const int tile = blockIdx.x;
    const int bb   = blockIdx.y;
    const int t0   = tile * TT;

    // Pre-zero halo rows that fall before t=0 (only tile 0; never overwritten by cp.async)
    if (t0 == 0) {
        for (int i = tid; i < (TC - 1) * FD; i += NTHREADS) {
            int r = i / FD, ff = i % FD;
            slab[0][r][ff] = 0.f;
            slab[1][r][ff] = 0.f;
        }
    }

    // --- loader precompute: 576 float4 per slab, 3 per thread ---
    int  lr[3], lq[3];
    long goff[3];
    bool lv[3];
#pragma unroll
    for (int j = 0; j < 3; ++j) {
        int i = tid + j * NTHREADS;
        lr[j] = i / (FD / 4);           // 24 float4 per row
        lq[j] = i % (FD / 4);
        int gt = t0 - (TC - 1) + lr[j]; // global t of this row
        lv[j] = (gt >= 0);              // gt <= TD-1 always (tiles cover T exactly)
        goff[j] = (long)gt * FD + lq[j] * 4;
    }
    const size_t xb = (size_t)bb * CD * TD * FD;

    auto issue = [&](int buf, int c) {
        const float* src = x + xb + (size_t)c * TD * FD;
#pragma unroll
        for (int j = 0; j < 3; ++j)
            if (lv[j]) cp_async16(&slab[buf][lr[j]][lq[j] * 4], src + goff[j]);
        asm volatile("cp.async.commit_group;\n" ::: "memory");
    };

    issue(0, 0);

    // accumulators: o=0 in low lane, o=1 in high lane; init with bias
    unsigned long long acc[TPG];
    {
        const float2 bv = *reinterpret_cast<const float2*>(bias + f * 2);
        const unsigned long long bp = pack2(bv.x, bv.y);
#pragma unroll
        for (int i = 0; i < TPG; ++i) acc[i] = bp;
    }

    const int tbase = tg * TPG;  // this thread's first window row in the slab
    // weights for lane f: w + f*640 floats; as u64, [c*5 + k] = (w[f,c,k,0], w[f,c,k,1])
    const unsigned long long* __restrict__ wbase =
        reinterpret_cast<const unsigned long long*>(w + (size_t)f * (CD * TC * 2));

    for (int c = 0; c < CD; ++c) {
        const int cur = c & 1;
        if (c + 1 < CD) {
            issue(cur ^ 1, c + 1);
            asm volatile("cp.async.wait_group 1;\n" ::: "memory");
        } else {
            asm volatile("cp.async.wait_group 0;\n" ::: "memory");
        }
        __syncthreads();   // slab[cur] complete & visible block-wide

        unsigned long long wv[TC];
        const unsigned long long* wp = wbase + c * TC;
#pragma unroll
        for (int k = 0; k < TC; ++k) wv[k] = wp[k];

        unsigned long long xv[TPG + TC - 1];
#pragma unroll
        for (int r = 0; r < TPG + TC - 1; ++r) {
            float s = slab[cur][tbase + r][f];
            xv[r] = pack2(s, s);
        }

#pragma unroll
        for (int tt = 0; tt < TPG; ++tt) {
#pragma unroll
            for (int k = 0; k < TC; ++k)
                ffma2(acc[tt], xv[tt + k], wv[k]);
        }
        __syncthreads();   // everyone done reading slab[cur] before it is refilled
    }

    // out[b][o][t][f]: f contiguous, t stride 96, o stride 96000, b stride 192000
    const int os = TD * FD;
    float* outp = out + (size_t)bb * 2 * os + (size_t)(t0 + tbase) * FD + f;
#pragma unroll
    for (int tt = 0; tt < TPG; ++tt) {
        float lo, hi;
        unpack2(acc[tt], lo, hi);
        outp[tt * FD]      = lo;   // o = 0
        outp[os + tt * FD] = hi;   // o = 1
    }
}

extern "C" void kernel_launch(void* const* d_in, const int* in_sizes, int n_in,
                              void* d_out, int out_size)
{
    const float* x    = (const float*)d_in[0];
    const float* w    = (const float*)d_in[1];
    const float* bias = (const float*)d_in[2];
    float* out        = (float*)d_out;

    dim3 grid(NTILES, 4);   // 50 t-tiles x B=4 = 200 blocks
    decoder_out_kernel<<<grid, NTHREADS>>>(x, w, bias, out);
}